// round 14
// baseline (speedup 1.0000x reference)
#include <cuda_runtime.h>
#include <cuda_bf16.h>
#include <stdint.h>

// ============================================================================
// MMD loss, two kernels:
//  1) stats: row norms + colsum PARTIALS + bf16 frag permute (no serial tail —
//     all 256 CTAs exit together).
//  2) GEMM (R9 exact: k32 chunks, 4 stages, batched frag LDS): CTA 0 computes
//     the bandwidth from the partials BEFORE its tile, overlapped with other
//     CTAs' mainloops; everyone spin-checks g_ready only at the epilogue
//     (~20us after it's set -> never blocks). exp2-based 5-kernel epilogue.
// ============================================================================

#define NROWS 4096
#define D     256
#define M_TOT 8192

__device__ float    g_sq[M_TOT];
__device__ float    g_colsum_part[256][256];
__device__ float    g_inv_b16;                // log2(e)/(16*bw)
__device__ float    g_part[1024];
__device__ int      g_ctr2;
__device__ volatile int g_ready;
// bf16x2 fragment-major operands: [tile(256)][tk16(16)][lane(32)][4 regs]
__device__ uint32_t g_Aperm[NROWS * D / 2];
__device__ uint32_t g_Bperm[NROWS * D / 2];

// ---------------------------------------------------------------------------
__device__ __forceinline__ uint32_t smem_u32(const void* p) {
    uint32_t a;
    asm("{ .reg .u64 t; cvta.to.shared.u64 t, %1; cvt.u32.u64 %0, t; }"
        : "=r"(a) : "l"(p));
    return a;
}
__device__ __forceinline__ void cp_async16(uint32_t s, const void* g) {
    asm volatile("cp.async.cg.shared.global [%0], [%1], 16;"
                 :: "r"(s), "l"(g) : "memory");
}
#define CP_COMMIT() asm volatile("cp.async.commit_group;" ::: "memory")
#define CP_WAIT(n)  asm volatile("cp.async.wait_group %0;" :: "n"(n) : "memory")

__device__ __forceinline__ uint32_t pack_bf16x2(float lo, float hi) {
    uint32_t r;
    asm("cvt.rn.bf16x2.f32 %0, %1, %2;" : "=r"(r) : "f"(hi), "f"(lo));
    return r;
}

__device__ __forceinline__ void mma_bf16(float* c, uint32_t a0, uint32_t a1,
                                         uint32_t a2, uint32_t a3,
                                         uint32_t b0, uint32_t b1) {
    asm volatile(
        "mma.sync.aligned.m16n8k16.row.col.f32.bf16.bf16.f32 "
        "{%0,%1,%2,%3}, {%4,%5,%6,%7}, {%8,%9}, {%0,%1,%2,%3};"
        : "+f"(c[0]), "+f"(c[1]), "+f"(c[2]), "+f"(c[3])
        : "r"(a0), "r"(a1), "r"(a2), "r"(a3), "r"(b0), "r"(b1));
}

// ---------------------------------------------------------------------------
// Kernel 1: stats slices + bf16 fragment permute. 256 blocks x 256 threads.
// NO serial reduction tail: colsum stays as 256 partial rows.
// ---------------------------------------------------------------------------
__global__ __launch_bounds__(256) void stats_kernel(const float* __restrict__ src,
                                                    const float* __restrict__ tgt) {
    const int blk = blockIdx.x, tid = threadIdx.x;
    const int w = tid >> 5, lane = tid & 31;
    const bool isA = (blk < 128);
    const int base = isA ? blk * 32 : (blk - 128) * 32;
    const float* sbase = (isA ? src : tgt) + (size_t)base * D;

    __shared__ float tile[32][260];

    #pragma unroll
    for (int i = tid; i < 2048; i += 256) {
        const int r = i >> 6, c4 = (i & 63) * 4;
        float4 v = *(const float4*)(sbase + (size_t)r * D + c4);
        tile[r][c4] = v.x; tile[r][c4 + 1] = v.y;
        tile[r][c4 + 2] = v.z; tile[r][c4 + 3] = v.w;
    }
    __syncthreads();

    float cs = 0.f;
    #pragma unroll 8
    for (int r = 0; r < 32; r++) cs += tile[r][tid];
    g_colsum_part[blk][tid] = cs;

    #pragma unroll
    for (int rr = 0; rr < 4; rr++) {
        const int r = w * 4 + rr;
        float sq = 0.f;
        #pragma unroll
        for (int j = 0; j < 8; j++) {
            const float x = tile[r][lane + 32 * j];
            sq += x * x;
        }
        #pragma unroll
        for (int off = 16; off > 0; off >>= 1) sq += __shfl_xor_sync(0xffffffffu, sq, off);
        if (lane == 0) g_sq[(isA ? 0 : NROWS) + base + r] = sq;
    }

    const int tile0 = (isA ? blk : blk - 128) * 2;
    uint4* dst = (uint4*)(isA ? g_Aperm : g_Bperm);
    #pragma unroll
    for (int i = tid; i < 1024; i += 256) {
        const int sub = i >> 9, tk = (i >> 5) & 15, l = i & 31;
        const int g = l >> 2, t = l & 3;
        const int r0 = sub * 16 + g, r1 = r0 + 8, c = tk * 16 + 2 * t;
        uint4 v;
        if (isA) {
            v.x = pack_bf16x2(tile[r0][c],     tile[r0][c + 1]);
            v.y = pack_bf16x2(tile[r1][c],     tile[r1][c + 1]);
            v.z = pack_bf16x2(tile[r0][c + 8], tile[r0][c + 9]);
            v.w = pack_bf16x2(tile[r1][c + 8], tile[r1][c + 9]);
        } else {
            v.x = pack_bf16x2(tile[r0][c],     tile[r0][c + 1]);
            v.y = pack_bf16x2(tile[r0][c + 8], tile[r0][c + 9]);
            v.z = pack_bf16x2(tile[r1][c],     tile[r1][c + 1]);
            v.w = pack_bf16x2(tile[r1][c + 8], tile[r1][c + 9]);
        }
        dst[(size_t)(tile0 + sub) * 512 + (tk * 32 + l)] = v;
    }
}

// ---------------------------------------------------------------------------
// Kernel 2: bf16 mma GEMM + fused exp epilogue (R9 structure).
// 1024 CTAs x 256 threads; CTA 128x128, warp 32x64, k32 chunks, 4 stages.
// CTA 0 computes the bandwidth first (overlapped with other CTAs' mainloops).
// ---------------------------------------------------------------------------
#define OPND_BYTES 8192
#define BUF_BYTES  16384
#define NSTAGE     4
#define SMEM_TJ    (NSTAGE * BUF_BYTES)       // 65536
#define SMEM_RED   (SMEM_TJ + 512)
#define SMEM_TOT   (SMEM_RED + 64)

__global__ __launch_bounds__(256, 2)
void mmd_mma_kernel(float* __restrict__ out) {
    extern __shared__ char smem[];
    const uint32_t sb = smem_u32(smem);
    const int tid = threadIdx.x, wid = tid >> 5, lane = tid & 31;
    const int g = lane >> 2, t = lane & 3;
    const int warp_m = wid & 3, warp_n = wid >> 2;
    const int bx = blockIdx.x, by = blockIdx.y;

    // ---- CTA 0: compute bandwidth from partials (overlaps others' GEMMs) ----
    if (bx == 0 && by == 0) {
        float csum = 0.f;
        #pragma unroll 16
        for (int p = 0; p < 256; p++) csum += g_colsum_part[p][tid];
        double ssq = (double)csum * (double)csum;
        double sumsq = 0.0;
        #pragma unroll 8
        for (int m = 0; m < M_TOT / 256; m++) sumsq += (double)g_sq[tid + m * 256];

        __shared__ double r1s[256], r2s[256];
        r1s[tid] = ssq; r2s[tid] = sumsq;
        __syncthreads();
        for (int st = 128; st > 0; st >>= 1) {
            if (tid < st) { r1s[tid] += r1s[tid + st]; r2s[tid] += r2s[tid + st]; }
            __syncthreads();
        }
        if (tid == 0) {
            const double M = (double)M_TOT;
            double sumL2 = 2.0 * M * r2s[0] - 2.0 * r1s[0];
            double bw = sumL2 / (M * M - M) / 4.0;
            g_inv_b16 = (float)(1.4426950408889634 / (bw * 16.0));
            __threadfence();
            g_ready = 1;
        }
        __syncthreads();   // r1s/r2s smem dead before GEMM reuse
    }

    // ---- regular GEMM tile ----
    float* tjs = (float*)(smem + SMEM_TJ);
    if (tid < 128) tjs[tid] = g_sq[NROWS + bx * 128 + tid];

    float acc[2][8][4];
    #pragma unroll
    for (int i = 0; i < 2; i++)
        #pragma unroll
        for (int j = 0; j < 8; j++)
            #pragma unroll
            for (int k = 0; k < 4; k++) acc[i][j][k] = 0.f;

    auto stage = [&](int kc, int buf) {
        const uint32_t sbuf = sb + buf * BUF_BYTES;
        #pragma unroll
        for (int v = 0; v < 2; v++) {
            const int soff = v * 4096 + tid * 16;
            const int seg = soff >> 9, within = soff & 511;
            const size_t ga = (((size_t)(by * 8 + (seg >> 1)) * 16 + kc * 2 + (seg & 1)) << 9) + within;
            cp_async16(sbuf + soff, (const char*)g_Aperm + ga);
            const size_t gb = (((size_t)(bx * 8 + (seg >> 1)) * 16 + kc * 2 + (seg & 1)) << 9) + within;
            cp_async16(sbuf + OPND_BYTES + soff, (const char*)g_Bperm + gb);
        }
    };

    stage(0, 0); CP_COMMIT();
    stage(1, 1); CP_COMMIT();
    stage(2, 2); CP_COMMIT();

    #pragma unroll
    for (int kc = 0; kc < 8; kc++) {
        if (kc < 6)       CP_WAIT(2);
        else if (kc == 6) CP_WAIT(1);
        else              CP_WAIT(0);
        __syncthreads();
        if (kc < 5) { stage(kc + 3, (kc + 3) & 3); CP_COMMIT(); }

        const uint4* As = (const uint4*)(smem + (kc & 3) * BUF_BYTES);
        const uint4* Bs = (const uint4*)(smem + (kc & 3) * BUF_BYTES + OPND_BYTES);

        // batch all 12 fragment LDS, then 32 back-to-back HMMAs
        uint4 a[2][2], b[2][4];
        #pragma unroll
        for (int ks = 0; ks < 2; ks++) {
            #pragma unroll
            for (int mt = 0; mt < 2; mt++)
                a[ks][mt] = As[((warp_m * 2 + mt) * 2 + ks) * 32 + lane];
            #pragma unroll
            for (int pp = 0; pp < 4; pp++)
                b[ks][pp] = Bs[((warp_n * 4 + pp) * 2 + ks) * 32 + lane];
        }
        #pragma unroll
        for (int ks = 0; ks < 2; ks++)
            #pragma unroll
            for (int mt = 0; mt < 2; mt++)
                #pragma unroll
                for (int pp = 0; pp < 4; pp++) {
                    mma_bf16(acc[mt][2 * pp],     a[ks][mt].x, a[ks][mt].y, a[ks][mt].z, a[ks][mt].w,
                             b[ks][pp].x, b[ks][pp].y);
                    mma_bf16(acc[mt][2 * pp + 1], a[ks][mt].x, a[ks][mt].y, a[ks][mt].z, a[ks][mt].w,
                             b[ks][pp].z, b[ks][pp].w);
                }
    }

    // bandwidth ready? (set ~3us in by CTA 0; mainloop takes ~20us - no block)
    if (tid == 0) {
        while (g_ready == 0) __nanosleep(64);
    }
    __syncthreads();
    __threadfence();   // acquire g_inv_b16

    // epilogue: L2 -> 5-kernel exp sum (exp2-based)
    const float inv_b16 = g_inv_b16;
    float si[2][2];
    #pragma unroll
    for (int mt = 0; mt < 2; mt++) {
        const int r0 = by * 128 + warp_m * 32 + mt * 16 + g;
        si[mt][0] = g_sq[r0];
        si[mt][1] = g_sq[r0 + 8];
    }

    float ksum = 0.f;
    #pragma unroll
    for (int nt = 0; nt < 8; nt++) {
        const int c0 = warp_n * 64 + nt * 8 + 2 * t;
        const float tj0 = tjs[c0], tj1 = tjs[c0 + 1];
        #pragma unroll
        for (int mt = 0; mt < 2; mt++) {
            const float* c = acc[mt][nt];
            #pragma unroll
            for (int q = 0; q < 4; q++) {
                const float L2 = si[mt][q >> 1] + ((q & 1) ? tj1 : tj0) - 2.f * c[q];
                const float e = exp2f(-L2 * inv_b16);
                const float e2 = e * e, e4 = e2 * e2, e8 = e4 * e4;
                ksum += e + e2 + e4 + e8 + e8 * e8;
            }
        }
    }

    #pragma unroll
    for (int off = 16; off > 0; off >>= 1) ksum += __shfl_xor_sync(0xffffffffu, ksum, off);
    float* red = (float*)(smem + SMEM_RED);
    if (lane == 0) red[wid] = ksum;
    __syncthreads();
    if (tid == 0) {
        float bsum = 0.f;
        #pragma unroll
        for (int i = 0; i < 8; i++) bsum += red[i];
        g_part[by * 32 + bx] = bsum;
    }

    // last-CTA tail: final loss + replay resets
    __shared__ int is_last;
    __threadfence();
    if (tid == 0) is_last = (atomicAdd(&g_ctr2, 1) == 1023);
    __syncthreads();
    if (!is_last) return;
    __threadfence();

    double sacc = 0.0;
    #pragma unroll
    for (int m = 0; m < 4; m++) sacc += (double)g_part[tid + m * 256];
    __shared__ double dred[256];
    dred[tid] = sacc;
    __syncthreads();
    for (int st = 128; st > 0; st >>= 1) {
        if (tid < st) dred[tid] += dred[tid + st];
        __syncthreads();
    }
    if (tid == 0) {
        double mean = dred[0] / ((double)NROWS * (double)NROWS);
        out[0] = (float)(-2.0 * mean);
        g_ctr2 = 0;
        g_ready = 0;   // reset for next graph replay (all CTAs already passed)
    }
}

// ---------------------------------------------------------------------------
extern "C" void kernel_launch(void* const* d_in, const int* in_sizes, int n_in,
                              void* d_out, int out_size) {
    (void)in_sizes; (void)n_in; (void)out_size;
    const float* src = (const float*)d_in[0];
    const float* tgt = (const float*)d_in[1];
    float* out = (float*)d_out;

    cudaFuncSetAttribute(mmd_mma_kernel, cudaFuncAttributeMaxDynamicSharedMemorySize,
                         SMEM_TOT);

    stats_kernel<<<256, 256>>>(src, tgt);
    mmd_mma_kernel<<<dim3(32, 32), 256, SMEM_TOT>>>(out);
}

// round 15
// speedup vs baseline: 1.0792x; 1.0792x over previous
#include <cuda_runtime.h>
#include <cuda_bf16.h>
#include <stdint.h>

// ============================================================================
// MMD loss, two kernels — assembly of the best measured components:
//  1) stats (R6): row norms + colsums + hierarchical bandwidth tail + bf16
//     fragment permute. 256 blocks x 256 threads.
//  2) GEMM (R9): grid 1024, CTA 128x128, warp 32x64, bf16 m16n8k16 mma.sync,
//     k32 chunks, 4-stage cp.async, batched fragment LDS, exp2 epilogue.
// ============================================================================

#define NROWS 4096
#define D     256
#define M_TOT 8192

__device__ float    g_sq[M_TOT];
__device__ float    g_colsum_part[256][256];
__device__ float    g_colsum_l2[16][256];
__device__ float    g_inv_b16;                // log2(e)/(16*bw)
__device__ float    g_part[1024];
__device__ int      g_ctr_grp[16];
__device__ int      g_ctr1;
__device__ int      g_ctr2;
// bf16x2 fragment-major operands: [tile(256)][tk16(16)][lane(32)][4 regs]
__device__ uint32_t g_Aperm[NROWS * D / 2];
__device__ uint32_t g_Bperm[NROWS * D / 2];

// ---------------------------------------------------------------------------
__device__ __forceinline__ uint32_t smem_u32(const void* p) {
    uint32_t a;
    asm("{ .reg .u64 t; cvta.to.shared.u64 t, %1; cvt.u32.u64 %0, t; }"
        : "=r"(a) : "l"(p));
    return a;
}
__device__ __forceinline__ void cp_async16(uint32_t s, const void* g) {
    asm volatile("cp.async.cg.shared.global [%0], [%1], 16;"
                 :: "r"(s), "l"(g) : "memory");
}
#define CP_COMMIT() asm volatile("cp.async.commit_group;" ::: "memory")
#define CP_WAIT(n)  asm volatile("cp.async.wait_group %0;" :: "n"(n) : "memory")

__device__ __forceinline__ uint32_t pack_bf16x2(float lo, float hi) {
    uint32_t r;
    asm("cvt.rn.bf16x2.f32 %0, %1, %2;" : "=r"(r) : "f"(hi), "f"(lo));
    return r;
}

__device__ __forceinline__ void mma_bf16(float* c, uint32_t a0, uint32_t a1,
                                         uint32_t a2, uint32_t a3,
                                         uint32_t b0, uint32_t b1) {
    asm volatile(
        "mma.sync.aligned.m16n8k16.row.col.f32.bf16.bf16.f32 "
        "{%0,%1,%2,%3}, {%4,%5,%6,%7}, {%8,%9}, {%0,%1,%2,%3};"
        : "+f"(c[0]), "+f"(c[1]), "+f"(c[2]), "+f"(c[3])
        : "r"(a0), "r"(a1), "r"(a2), "r"(a3), "r"(b0), "r"(b1));
}

// ---------------------------------------------------------------------------
// Kernel 1: stats + bf16 fragment permute (R6 — best measured, 13.7us wall).
// ---------------------------------------------------------------------------
__global__ __launch_bounds__(256) void stats_kernel(const float* __restrict__ src,
                                                    const float* __restrict__ tgt) {
    const int blk = blockIdx.x, tid = threadIdx.x;
    const int w = tid >> 5, lane = tid & 31;
    const bool isA = (blk < 128);
    const int base = isA ? blk * 32 : (blk - 128) * 32;
    const float* sbase = (isA ? src : tgt) + (size_t)base * D;

    __shared__ float tile[32][260];

    #pragma unroll
    for (int i = tid; i < 2048; i += 256) {
        const int r = i >> 6, c4 = (i & 63) * 4;
        float4 v = *(const float4*)(sbase + (size_t)r * D + c4);
        tile[r][c4] = v.x; tile[r][c4 + 1] = v.y;
        tile[r][c4 + 2] = v.z; tile[r][c4 + 3] = v.w;
    }
    __syncthreads();

    float cs = 0.f;
    #pragma unroll 8
    for (int r = 0; r < 32; r++) cs += tile[r][tid];
    g_colsum_part[blk][tid] = cs;

    #pragma unroll
    for (int rr = 0; rr < 4; rr++) {
        const int r = w * 4 + rr;
        float sq = 0.f;
        #pragma unroll
        for (int j = 0; j < 8; j++) {
            const float x = tile[r][lane + 32 * j];
            sq += x * x;
        }
        #pragma unroll
        for (int off = 16; off > 0; off >>= 1) sq += __shfl_xor_sync(0xffffffffu, sq, off);
        if (lane == 0) g_sq[(isA ? 0 : NROWS) + base + r] = sq;
    }

    const int tile0 = (isA ? blk : blk - 128) * 2;
    uint4* dst = (uint4*)(isA ? g_Aperm : g_Bperm);
    #pragma unroll
    for (int i = tid; i < 1024; i += 256) {
        const int sub = i >> 9, tk = (i >> 5) & 15, l = i & 31;
        const int g = l >> 2, t = l & 3;
        const int r0 = sub * 16 + g, r1 = r0 + 8, c = tk * 16 + 2 * t;
        uint4 v;
        if (isA) {
            v.x = pack_bf16x2(tile[r0][c],     tile[r0][c + 1]);
            v.y = pack_bf16x2(tile[r1][c],     tile[r1][c + 1]);
            v.z = pack_bf16x2(tile[r0][c + 8], tile[r0][c + 9]);
            v.w = pack_bf16x2(tile[r1][c + 8], tile[r1][c + 9]);
        } else {
            v.x = pack_bf16x2(tile[r0][c],     tile[r0][c + 1]);
            v.y = pack_bf16x2(tile[r0][c + 8], tile[r0][c + 9]);
            v.z = pack_bf16x2(tile[r1][c],     tile[r1][c + 1]);
            v.w = pack_bf16x2(tile[r1][c + 8], tile[r1][c + 9]);
        }
        dst[(size_t)(tile0 + sub) * 512 + (tk * 32 + l)] = v;
    }

    __shared__ int flag1;
    __threadfence();
    if (tid == 0) flag1 = (atomicAdd(&g_ctr_grp[blk >> 4], 1) == 15);
    __syncthreads();
    if (!flag1) return;

    const int grp = blk >> 4;
    float gs = 0.f;
    #pragma unroll
    for (int p = 0; p < 16; p++) gs += g_colsum_part[grp * 16 + p][tid];
    g_colsum_l2[grp][tid] = gs;

    __shared__ int flag2;
    __threadfence();
    if (tid == 0) flag2 = (atomicAdd(&g_ctr1, 1) == 15);
    __syncthreads();
    if (!flag2) return;

    float csum = 0.f;
    #pragma unroll
    for (int p = 0; p < 16; p++) csum += g_colsum_l2[p][tid];
    double ssq = (double)csum * (double)csum;
    double sumsq = 0.0;
    #pragma unroll 8
    for (int m = 0; m < M_TOT / 256; m++) sumsq += (double)g_sq[tid + m * 256];

    __shared__ double r1s[256], r2s[256];
    r1s[tid] = ssq; r2s[tid] = sumsq;
    __syncthreads();
    for (int st = 128; st > 0; st >>= 1) {
        if (tid < st) { r1s[tid] += r1s[tid + st]; r2s[tid] += r2s[tid + st]; }
        __syncthreads();
    }
    if (tid == 0) {
        const double M = (double)M_TOT;
        double sumL2 = 2.0 * M * r2s[0] - 2.0 * r1s[0];
        double bw = sumL2 / (M * M - M) / 4.0;
        g_inv_b16 = (float)(1.4426950408889634 / (bw * 16.0));
        g_ctr1 = 0;
    }
    if (tid < 16) g_ctr_grp[tid] = 0;   // reset for graph replay
}

// ---------------------------------------------------------------------------
// Kernel 2: bf16 mma GEMM + fused exp epilogue (R9 — best measured, 37.66us).
// 1024 CTAs x 256 threads; CTA 128x128, warp 32x64, k32 chunks, 4 stages.
// ---------------------------------------------------------------------------
#define OPND_BYTES 8192
#define BUF_BYTES  16384
#define NSTAGE     4
#define SMEM_TJ    (NSTAGE * BUF_BYTES)       // 65536
#define SMEM_RED   (SMEM_TJ + 512)
#define SMEM_TOT   (SMEM_RED + 64)

__global__ __launch_bounds__(256, 2)
void mmd_mma_kernel(float* __restrict__ out) {
    extern __shared__ char smem[];
    const uint32_t sb = smem_u32(smem);
    const int tid = threadIdx.x, wid = tid >> 5, lane = tid & 31;
    const int g = lane >> 2, t = lane & 3;
    const int warp_m = wid & 3, warp_n = wid >> 2;
    const int bx = blockIdx.x, by = blockIdx.y;

    float* tjs = (float*)(smem + SMEM_TJ);
    if (tid < 128) tjs[tid] = g_sq[NROWS + bx * 128 + tid];

    float acc[2][8][4];
    #pragma unroll
    for (int i = 0; i < 2; i++)
        #pragma unroll
        for (int j = 0; j < 8; j++)
            #pragma unroll
            for (int k = 0; k < 4; k++) acc[i][j][k] = 0.f;

    auto stage = [&](int kc, int buf) {
        const uint32_t sbuf = sb + buf * BUF_BYTES;
        #pragma unroll
        for (int v = 0; v < 2; v++) {
            const int soff = v * 4096 + tid * 16;
            const int seg = soff >> 9, within = soff & 511;
            const size_t ga = (((size_t)(by * 8 + (seg >> 1)) * 16 + kc * 2 + (seg & 1)) << 9) + within;
            cp_async16(sbuf + soff, (const char*)g_Aperm + ga);
            const size_t gb = (((size_t)(bx * 8 + (seg >> 1)) * 16 + kc * 2 + (seg & 1)) << 9) + within;
            cp_async16(sbuf + OPND_BYTES + soff, (const char*)g_Bperm + gb);
        }
    };

    stage(0, 0); CP_COMMIT();
    stage(1, 1); CP_COMMIT();
    stage(2, 2); CP_COMMIT();

    #pragma unroll
    for (int kc = 0; kc < 8; kc++) {
        if (kc < 6)       CP_WAIT(2);
        else if (kc == 6) CP_WAIT(1);
        else              CP_WAIT(0);
        __syncthreads();
        if (kc < 5) { stage(kc + 3, (kc + 3) & 3); CP_COMMIT(); }

        const uint4* As = (const uint4*)(smem + (kc & 3) * BUF_BYTES);
        const uint4* Bs = (const uint4*)(smem + (kc & 3) * BUF_BYTES + OPND_BYTES);

        // batch all 12 fragment LDS, then 32 back-to-back HMMAs
        uint4 a[2][2], b[2][4];
        #pragma unroll
        for (int ks = 0; ks < 2; ks++) {
            #pragma unroll
            for (int mt = 0; mt < 2; mt++)
                a[ks][mt] = As[((warp_m * 2 + mt) * 2 + ks) * 32 + lane];
            #pragma unroll
            for (int pp = 0; pp < 4; pp++)
                b[ks][pp] = Bs[((warp_n * 4 + pp) * 2 + ks) * 32 + lane];
        }
        #pragma unroll
        for (int ks = 0; ks < 2; ks++)
            #pragma unroll
            for (int mt = 0; mt < 2; mt++)
                #pragma unroll
                for (int pp = 0; pp < 4; pp++) {
                    mma_bf16(acc[mt][2 * pp],     a[ks][mt].x, a[ks][mt].y, a[ks][mt].z, a[ks][mt].w,
                             b[ks][pp].x, b[ks][pp].y);
                    mma_bf16(acc[mt][2 * pp + 1], a[ks][mt].x, a[ks][mt].y, a[ks][mt].z, a[ks][mt].w,
                             b[ks][pp].z, b[ks][pp].w);
                }
    }

    // epilogue: L2 -> 5-kernel exp sum (exp2-based)
    const float inv_b16 = g_inv_b16;
    float si[2][2];
    #pragma unroll
    for (int mt = 0; mt < 2; mt++) {
        const int r0 = by * 128 + warp_m * 32 + mt * 16 + g;
        si[mt][0] = g_sq[r0];
        si[mt][1] = g_sq[r0 + 8];
    }

    float ksum = 0.f;
    #pragma unroll
    for (int nt = 0; nt < 8; nt++) {
        const int c0 = warp_n * 64 + nt * 8 + 2 * t;
        const float tj0 = tjs[c0], tj1 = tjs[c0 + 1];
        #pragma unroll
        for (int mt = 0; mt < 2; mt++) {
            const float* c = acc[mt][nt];
            #pragma unroll
            for (int q = 0; q < 4; q++) {
                const float L2 = si[mt][q >> 1] + ((q & 1) ? tj1 : tj0) - 2.f * c[q];
                const float e = exp2f(-L2 * inv_b16);
                const float e2 = e * e, e4 = e2 * e2, e8 = e4 * e4;
                ksum += e + e2 + e4 + e8 + e8 * e8;
            }
        }
    }

    #pragma unroll
    for (int off = 16; off > 0; off >>= 1) ksum += __shfl_xor_sync(0xffffffffu, ksum, off);
    float* red = (float*)(smem + SMEM_RED);
    if (lane == 0) red[wid] = ksum;
    __syncthreads();
    if (tid == 0) {
        float bsum = 0.f;
        #pragma unroll
        for (int i = 0; i < 8; i++) bsum += red[i];
        g_part[by * 32 + bx] = bsum;
    }

    // last-CTA tail: final loss
    __shared__ int is_last;
    __threadfence();
    if (tid == 0) is_last = (atomicAdd(&g_ctr2, 1) == 1023);
    __syncthreads();
    if (!is_last) return;
    __threadfence();

    double sacc = 0.0;
    #pragma unroll
    for (int m = 0; m < 4; m++) sacc += (double)g_part[tid + m * 256];
    __shared__ double dred[256];
    dred[tid] = sacc;
    __syncthreads();
    for (int st = 128; st > 0; st >>= 1) {
        if (tid < st) dred[tid] += dred[tid + st];
        __syncthreads();
    }
    if (tid == 0) {
        double mean = dred[0] / ((double)NROWS * (double)NROWS);
        out[0] = (float)(-2.0 * mean);
        g_ctr2 = 0;
    }
}

// ---------------------------------------------------------------------------
extern "C" void kernel_launch(void* const* d_in, const int* in_sizes, int n_in,
                              void* d_out, int out_size) {
    (void)in_sizes; (void)n_in; (void)out_size;
    const float* src = (const float*)d_in[0];
    const float* tgt = (const float*)d_in[1];
    float* out = (float*)d_out;

    cudaFuncSetAttribute(mmd_mma_kernel, cudaFuncAttributeMaxDynamicSharedMemorySize,
                         SMEM_TOT);

    stats_kernel<<<256, 256>>>(src, tgt);
    mmd_mma_kernel<<<dim3(32, 32), 256, SMEM_TOT>>>(out);
}